// round 11
// baseline (speedup 1.0000x reference)
#include <cuda_runtime.h>
#include <math.h>

// Problem constants (fixed by the dataset)
#define NU 60000
#define NI 40000
#define NN 100000     // NU + NI
#define NE 500000
#define D  64
#define NF 4
#define NBLK 98       // ceil(NN/1024) for the scan
#define FULLM 0xFFFFFFFFu

// ---------------- static device scratch ----------------
__device__ float  g_ego0[NN * D];
__device__ float  g_ego1[NN * D];
__device__ float  g_all [NN * D];
__device__ float  g_tv0 [NN * D];    // tv double buffer
__device__ float  g_tv1 [NN * D];
__device__ float4 g_S4  [NE];        // raw S (written only on the final iteration)
__device__ float4 g_SsmA[NE];        // softmax(S) double buffer
__device__ float4 g_SsmB[NE];
__device__ float  g_dinv[NN];
__device__ int    g_deg [NN];
__device__ int    g_rowstart[NN + 1];
__device__ int    g_cnt [NN];
__device__ int    g_blocksum[NBLK];
__device__ float4 g_adj [2 * NE];    // {src, eid, enorm, unused}

// ---------------- setup kernels ----------------

// fused: ego0 = concat(user,item); all = ego0; tv0 = tanh(l2norm_factor(ego0))
// one warp per node
__global__ void k_init_tv(const float* __restrict__ u, const float* __restrict__ it) {
    int gw = (blockIdx.x * blockDim.x + threadIdx.x) >> 5;
    if (gw >= NN) return;
    int lane = threadIdx.x & 31;
    const float* srcp = (gw < NU) ? (u + (size_t)gw * D)
                                  : (it + (size_t)(gw - NU) * D);
    float2 a = reinterpret_cast<const float2*>(srcp)[lane];
    reinterpret_cast<float2*>(g_ego0 + (size_t)gw * D)[lane] = a;
    reinterpret_cast<float2*>(g_all  + (size_t)gw * D)[lane] = a;
    float ss = a.x * a.x + a.y * a.y;
    ss += __shfl_xor_sync(FULLM, ss, 1);
    ss += __shfl_xor_sync(FULLM, ss, 2);
    ss += __shfl_xor_sync(FULLM, ss, 4);
    float rinv = 1.0f / fmaxf(sqrtf(ss), 1e-12f);
    float2 o;
    o.x = tanhf(a.x * rinv);
    o.y = tanhf(a.y * rinv);
    reinterpret_cast<float2*>(g_tv0 + (size_t)gw * D)[lane] = o;
}

__global__ void k_deg(const int* __restrict__ ei) {
    int j = blockIdx.x * blockDim.x + threadIdx.x;
    if (j >= NE) return;
    atomicAdd(&g_deg[ei[j]], 1);
    atomicAdd(&g_deg[ei[NE + j]], 1);
}

// fused: dinv[n] = deg^-0.5 AND per-block partial sums of deg
__global__ void k_dinv_partial() {
    __shared__ int sh[1024];
    int t = threadIdx.x, n = blockIdx.x * 1024 + t;
    int d = (n < NN) ? g_deg[n] : 0;
    if (n < NN) g_dinv[n] = (d > 0) ? (1.0f / sqrtf((float)d)) : 0.0f;
    sh[t] = d;
    __syncthreads();
    for (int o = 512; o > 0; o >>= 1) {
        if (t < o) sh[t] += sh[t + o];
        __syncthreads();
    }
    if (t == 0) g_blocksum[blockIdx.x] = sh[0];
}

// parallel exclusive scan of NBLK block sums (one 128-thread block)
__global__ void k_scanblocks() {
    __shared__ int wsum[4];
    int t = threadIdx.x;                       // 0..127
    int v = (t < NBLK) ? g_blocksum[t] : 0;
    int x = v;
    for (int o = 1; o < 32; o <<= 1) {         // inclusive scan within warp
        int y = __shfl_up_sync(FULLM, x, o);
        if ((t & 31) >= o) x += y;
    }
    if ((t & 31) == 31) wsum[t >> 5] = x;
    __syncthreads();
    if (t == 0) {                              // tiny serial scan of 4 warp sums
        int acc = 0;
        for (int i = 0; i < 4; i++) { int w = wsum[i]; wsum[i] = acc; acc += w; }
    }
    __syncthreads();
    int base = wsum[t >> 5];
    if (t < NBLK) g_blocksum[t] = base + x - v;   // exclusive
    if (t == 0) g_rowstart[NN] = 2 * NE;
}

__global__ void k_offsets() {
    __shared__ int sh[1024];
    int t = threadIdx.x, n = blockIdx.x * 1024 + t;
    int v = (n < NN) ? g_deg[n] : 0;
    sh[t] = v;
    __syncthreads();
    for (int o = 1; o < 1024; o <<= 1) {
        int x = (t >= o) ? sh[t - o] : 0;
        __syncthreads();
        sh[t] += x;
        __syncthreads();
    }
    if (n < NN) g_rowstart[n] = g_blocksum[blockIdx.x] + sh[t] - v;
}

// fill CSR adjacency (both directions); forward thread also computes the
// initial softmax of the input S -> SsmA (fused, saves a separate pass)
__global__ void k_fill_sm(const int* __restrict__ ei, const float* __restrict__ S) {
    int d = blockIdx.x * blockDim.x + threadIdx.x;
    if (d >= 2 * NE) return;
    int j = (d < NE) ? d : d - NE;
    int r = ei[j], c = ei[NE + j];
    int src = (d < NE) ? r : c;
    int dst = (d < NE) ? c : r;
    int pos = g_rowstart[dst] + atomicAdd(&g_cnt[dst], 1);
    g_adj[pos] = make_float4(__int_as_float(src), __int_as_float(j),
                             g_dinv[src] * g_dinv[dst], 0.0f);
    if (d < NE) {
        float4 s = make_float4(S[j], S[NE + j], S[2 * NE + j], S[3 * NE + j]);
        float m  = fmaxf(fmaxf(s.x, s.y), fmaxf(s.z, s.w));
        float e0 = expf(s.x - m), e1 = expf(s.y - m);
        float e2 = expf(s.z - m), e3 = expf(s.w - m);
        float rr = 1.0f / (e0 + e1 + e2 + e3);
        g_SsmA[j] = make_float4(e0 * rr, e1 * rr, e2 * rr, e3 * rr);
    }
}

// broadcast source lane j's per-factor weight vector; return this lane's factor
__device__ __forceinline__ float bcast_w(float4 w4, int j, int kf) {
    float wx = __shfl_sync(FULLM, w4.x, j);
    float wy = __shfl_sync(FULLM, w4.y, j);
    float wz = __shfl_sync(FULLM, w4.z, j);
    float ww = __shfl_sync(FULLM, w4.w, j);
    return (kf == 0) ? wx : (kf == 1) ? wy : (kf == 2) ? wz : ww;
}

// conv over a batch of up to 32 adjacency entries held lane-wise in registers
// unrolled x8 for deeper MLP on the ego-row gathers
__device__ __forceinline__ void conv_batch(float2& acc, const float* __restrict__ ego,
                                           int src, float4 w4, int n, int lane, int kf) {
    int j = 0;
    for (; j + 8 <= n; j += 8) {
        int s0 = __shfl_sync(FULLM, src, j);
        int s1 = __shfl_sync(FULLM, src, j + 1);
        int s2 = __shfl_sync(FULLM, src, j + 2);
        int s3 = __shfl_sync(FULLM, src, j + 3);
        int s4 = __shfl_sync(FULLM, src, j + 4);
        int s5 = __shfl_sync(FULLM, src, j + 5);
        int s6 = __shfl_sync(FULLM, src, j + 6);
        int s7 = __shfl_sync(FULLM, src, j + 7);
        float2 v0 = *reinterpret_cast<const float2*>(ego + (size_t)s0 * D + lane * 2);
        float2 v1 = *reinterpret_cast<const float2*>(ego + (size_t)s1 * D + lane * 2);
        float2 v2 = *reinterpret_cast<const float2*>(ego + (size_t)s2 * D + lane * 2);
        float2 v3 = *reinterpret_cast<const float2*>(ego + (size_t)s3 * D + lane * 2);
        float2 v4 = *reinterpret_cast<const float2*>(ego + (size_t)s4 * D + lane * 2);
        float2 v5 = *reinterpret_cast<const float2*>(ego + (size_t)s5 * D + lane * 2);
        float2 v6 = *reinterpret_cast<const float2*>(ego + (size_t)s6 * D + lane * 2);
        float2 v7 = *reinterpret_cast<const float2*>(ego + (size_t)s7 * D + lane * 2);
        float w0 = bcast_w(w4, j,     kf);
        float w1 = bcast_w(w4, j + 1, kf);
        float w2 = bcast_w(w4, j + 2, kf);
        float w3 = bcast_w(w4, j + 3, kf);
        float w4_ = bcast_w(w4, j + 4, kf);
        float w5 = bcast_w(w4, j + 5, kf);
        float w6 = bcast_w(w4, j + 6, kf);
        float w7 = bcast_w(w4, j + 7, kf);
        acc.x += w0 * v0.x; acc.y += w0 * v0.y;
        acc.x += w1 * v1.x; acc.y += w1 * v1.y;
        acc.x += w2 * v2.x; acc.y += w2 * v2.y;
        acc.x += w3 * v3.x; acc.y += w3 * v3.y;
        acc.x += w4_ * v4.x; acc.y += w4_ * v4.y;
        acc.x += w5 * v5.x; acc.y += w5 * v5.y;
        acc.x += w6 * v6.x; acc.y += w6 * v6.y;
        acc.x += w7 * v7.x; acc.y += w7 * v7.y;
    }
    for (; j + 4 <= n; j += 4) {
        int s0 = __shfl_sync(FULLM, src, j);
        int s1 = __shfl_sync(FULLM, src, j + 1);
        int s2 = __shfl_sync(FULLM, src, j + 2);
        int s3 = __shfl_sync(FULLM, src, j + 3);
        float2 v0 = *reinterpret_cast<const float2*>(ego + (size_t)s0 * D + lane * 2);
        float2 v1 = *reinterpret_cast<const float2*>(ego + (size_t)s1 * D + lane * 2);
        float2 v2 = *reinterpret_cast<const float2*>(ego + (size_t)s2 * D + lane * 2);
        float2 v3 = *reinterpret_cast<const float2*>(ego + (size_t)s3 * D + lane * 2);
        float w0 = bcast_w(w4, j,     kf);
        float w1 = bcast_w(w4, j + 1, kf);
        float w2 = bcast_w(w4, j + 2, kf);
        float w3 = bcast_w(w4, j + 3, kf);
        acc.x += w0 * v0.x; acc.y += w0 * v0.y;
        acc.x += w1 * v1.x; acc.y += w1 * v1.y;
        acc.x += w2 * v2.x; acc.y += w2 * v2.y;
        acc.x += w3 * v3.x; acc.y += w3 * v3.y;
    }
    for (; j < n; j++) {
        int sj = __shfl_sync(FULLM, src, j);
        float2 v = *reinterpret_cast<const float2*>(ego + (size_t)sj * D + lane * 2);
        float wj = bcast_w(w4, j, kf);
        acc.x += wj * v.x; acc.y += wj * v.y;
    }
}

// score over a batch: returns pp (per-factor dot) for the edge owned by this lane
// unrolled x4 for deeper MLP on the tv-row gathers
__device__ __forceinline__ float4 score_batch(float2 acc, const float* __restrict__ tv,
                                              int item, int n, int lane) {
    float4 pp = make_float4(0, 0, 0, 0);
    int j = 0;
    for (; j + 4 <= n; j += 4) {
        int i0 = __shfl_sync(FULLM, item, j);
        int i1 = __shfl_sync(FULLM, item, j + 1);
        int i2 = __shfl_sync(FULLM, item, j + 2);
        int i3 = __shfl_sync(FULLM, item, j + 3);
        float2 t0 = *reinterpret_cast<const float2*>(tv + (size_t)i0 * D + lane * 2);
        float2 t1 = *reinterpret_cast<const float2*>(tv + (size_t)i1 * D + lane * 2);
        float2 t2 = *reinterpret_cast<const float2*>(tv + (size_t)i2 * D + lane * 2);
        float2 t3 = *reinterpret_cast<const float2*>(tv + (size_t)i3 * D + lane * 2);
        float pa = acc.x * t0.x + acc.y * t0.y;
        float pb = acc.x * t1.x + acc.y * t1.y;
        float pc = acc.x * t2.x + acc.y * t2.y;
        float pd = acc.x * t3.x + acc.y * t3.y;
        pa += __shfl_xor_sync(FULLM, pa, 1); pb += __shfl_xor_sync(FULLM, pb, 1);
        pc += __shfl_xor_sync(FULLM, pc, 1); pd += __shfl_xor_sync(FULLM, pd, 1);
        pa += __shfl_xor_sync(FULLM, pa, 2); pb += __shfl_xor_sync(FULLM, pb, 2);
        pc += __shfl_xor_sync(FULLM, pc, 2); pd += __shfl_xor_sync(FULLM, pd, 2);
        pa += __shfl_xor_sync(FULLM, pa, 4); pb += __shfl_xor_sync(FULLM, pb, 4);
        pc += __shfl_xor_sync(FULLM, pc, 4); pd += __shfl_xor_sync(FULLM, pd, 4);
        float qa0 = __shfl_sync(FULLM, pa, 0),  qa1 = __shfl_sync(FULLM, pa, 8);
        float qa2 = __shfl_sync(FULLM, pa, 16), qa3 = __shfl_sync(FULLM, pa, 24);
        float qb0 = __shfl_sync(FULLM, pb, 0),  qb1 = __shfl_sync(FULLM, pb, 8);
        float qb2 = __shfl_sync(FULLM, pb, 16), qb3 = __shfl_sync(FULLM, pb, 24);
        float qc0 = __shfl_sync(FULLM, pc, 0),  qc1 = __shfl_sync(FULLM, pc, 8);
        float qc2 = __shfl_sync(FULLM, pc, 16), qc3 = __shfl_sync(FULLM, pc, 24);
        float qd0 = __shfl_sync(FULLM, pd, 0),  qd1 = __shfl_sync(FULLM, pd, 8);
        float qd2 = __shfl_sync(FULLM, pd, 16), qd3 = __shfl_sync(FULLM, pd, 24);
        if (lane == j)     pp = make_float4(qa0, qa1, qa2, qa3);
        if (lane == j + 1) pp = make_float4(qb0, qb1, qb2, qb3);
        if (lane == j + 2) pp = make_float4(qc0, qc1, qc2, qc3);
        if (lane == j + 3) pp = make_float4(qd0, qd1, qd2, qd3);
    }
    for (; j < n; j++) {
        int ij = __shfl_sync(FULLM, item, j);
        float2 t = *reinterpret_cast<const float2*>(tv + (size_t)ij * D + lane * 2);
        float p = acc.x * t.x + acc.y * t.y;
        p += __shfl_xor_sync(FULLM, p, 1);
        p += __shfl_xor_sync(FULLM, p, 2);
        p += __shfl_xor_sync(FULLM, p, 4);
        float q0 = __shfl_sync(FULLM, p, 0),  q1 = __shfl_sync(FULLM, p, 8);
        float q2 = __shfl_sync(FULLM, p, 16), q3 = __shfl_sync(FULLM, p, 24);
        if (lane == j) pp = make_float4(q0, q1, q2, q3);
    }
    return pp;
}

// ---------------- fused conv + score + softmax, one warp per node ----------------
template <bool LASTIT, bool FINAL>
__global__ void __launch_bounds__(256)
k_fused(const float* __restrict__ ego, float* __restrict__ xn,
        const float* __restrict__ tv, float* __restrict__ tv_next,
        const float4* __restrict__ ssm_in, float4* __restrict__ ssm_out) {
    int gw = (blockIdx.x * blockDim.x + threadIdx.x) >> 5;
    if (gw >= NN) return;
    int lane = threadIdx.x & 31;
    int kf = lane >> 3;
    int s = g_rowstart[gw], e = g_rowstart[gw + 1];
    int deg = e - s;

    // ---- phase 1: conv (batch loop + carry registers) ----
    float2 acc = make_float2(0.0f, 0.0f);
    int c_src = 0, c_eid = 0;
    float4 c_sm = make_float4(0, 0, 0, 0);
    for (int b = s; b < e; b += 32) {
        int n = min(32, e - b);
        int src = 0;
        float4 w4 = make_float4(0, 0, 0, 0);
        if (lane < n) {
            float4 a = g_adj[b + lane];                 // coalesced batch load
            src = __float_as_int(a.x);
            float4 sm = ssm_in[__float_as_int(a.y)];    // 32 gathers in flight
            w4 = make_float4(sm.x * a.z, sm.y * a.z, sm.z * a.z, sm.w * a.z);
            c_src = src; c_eid = __float_as_int(a.y); c_sm = sm;   // carry
        }
        conv_batch(acc, ego, src, w4, n, lane, kf);
    }

    reinterpret_cast<float2*>(xn + (size_t)gw * D)[lane] = acc;

    // per-factor inverse norm (every lane ends with its 8-lane group's value)
    float ss = acc.x * acc.x + acc.y * acc.y;
    ss += __shfl_xor_sync(FULLM, ss, 1);
    ss += __shfl_xor_sync(FULLM, ss, 2);
    ss += __shfl_xor_sync(FULLM, ss, 4);
    float rinv = 1.0f / fmaxf(sqrtf(ss), 1e-12f);

    if (LASTIT) {
        float2* ap = reinterpret_cast<float2*>(g_all + (size_t)gw * D) + lane;
        float2 av = *ap;
        av.x += acc.x; av.y += acc.y;
        *ap = av;
        float2 t;
        t.x = tanhf(acc.x * rinv);
        t.y = tanhf(acc.y * rinv);
        reinterpret_cast<float2*>(tv_next + (size_t)gw * D)[lane] = t;
    }

    // ---- phase 2: score (user nodes only) ----
    if (gw >= NU) return;

    float r0 = __shfl_sync(FULLM, rinv, 0);
    float r1 = __shfl_sync(FULLM, rinv, 8);
    float r2 = __shfl_sync(FULLM, rinv, 16);
    float r3 = __shfl_sync(FULLM, rinv, 24);

    if (deg <= 32) {
        // reuse carried registers: c_src (=item), c_eid, c_sm (=raw ssm_in[eid])
        float4 pp = score_batch(acc, tv, c_src, deg, lane);
        if (lane < deg) {
            float4 sv = make_float4(c_sm.x + pp.x * r0, c_sm.y + pp.y * r1,
                                    c_sm.z + pp.z * r2, c_sm.w + pp.w * r3);
            if (FINAL) {
                g_S4[c_eid] = sv;
            } else {
                float m  = fmaxf(fmaxf(sv.x, sv.y), fmaxf(sv.z, sv.w));
                float e0 = expf(sv.x - m), e1 = expf(sv.y - m);
                float e2 = expf(sv.z - m), e3 = expf(sv.w - m);
                float rr = 1.0f / (e0 + e1 + e2 + e3);
                ssm_out[c_eid] = make_float4(e0 * rr, e1 * rr, e2 * rr, e3 * rr);
            }
        }
    } else {
        for (int b = s; b < e; b += 32) {
            int n = min(32, e - b);
            int item = 0, eid = 0;
            float4 svr = make_float4(0, 0, 0, 0);
            if (lane < n) {
                float4 a = g_adj[b + lane];
                item = __float_as_int(a.x);
                eid  = __float_as_int(a.y);
                svr  = ssm_in[eid];
            }
            float4 pp = score_batch(acc, tv, item, n, lane);
            if (lane < n) {
                float4 sv = make_float4(svr.x + pp.x * r0, svr.y + pp.y * r1,
                                        svr.z + pp.z * r2, svr.w + pp.w * r3);
                if (FINAL) {
                    g_S4[eid] = sv;
                } else {
                    float m  = fmaxf(fmaxf(sv.x, sv.y), fmaxf(sv.z, sv.w));
                    float e0 = expf(sv.x - m), e1 = expf(sv.y - m);
                    float e2 = expf(sv.z - m), e3 = expf(sv.w - m);
                    float rr = 1.0f / (e0 + e1 + e2 + e3);
                    ssm_out[eid] = make_float4(e0 * rr, e1 * rr, e2 * rr, e3 * rr);
                }
            }
        }
    }
}

// output S transpose [NE,4] -> [4,NE]
__global__ void k_transS_out(float* __restrict__ outS) {
    int j = blockIdx.x * blockDim.x + threadIdx.x;
    if (j >= NE) return;
    float4 s = g_S4[j];
    outS[j]          = s.x;
    outS[NE + j]     = s.y;
    outS[2 * NE + j] = s.z;
    outS[3 * NE + j] = s.w;
}

// ---------------- host orchestration ----------------

extern "C" void kernel_launch(void* const* d_in, const int* in_sizes, int n_in,
                              void* d_out, int out_size) {
    const float* user = (const float*)d_in[0];
    const float* item = (const float*)d_in[1];
    const float* Sin  = (const float*)d_in[2];
    const int*   ei   = (const int*)d_in[3];
    float* out = (float*)d_out;

    void *p_deg, *p_cnt, *p_ego0, *p_ego1, *p_all, *p_tv0, *p_tv1, *p_ssmA, *p_ssmB;
    cudaGetSymbolAddress(&p_deg,  g_deg);
    cudaGetSymbolAddress(&p_cnt,  g_cnt);
    cudaGetSymbolAddress(&p_ego0, g_ego0);
    cudaGetSymbolAddress(&p_ego1, g_ego1);
    cudaGetSymbolAddress(&p_all,  g_all);
    cudaGetSymbolAddress(&p_tv0,  g_tv0);
    cudaGetSymbolAddress(&p_tv1,  g_tv1);
    cudaGetSymbolAddress(&p_ssmA, g_SsmA);
    cudaGetSymbolAddress(&p_ssmB, g_SsmB);

    const int T = 256;
    const int gEdge  = (NE + T - 1) / T;
    const int gDir   = (2 * NE + T - 1) / T;
    const int gNodeW = (NN * 32 + T - 1) / T;

    // ---- setup (6 kernels + 2 memsets) ----
    cudaMemsetAsync(p_deg, 0, NN * sizeof(int), 0);
    cudaMemsetAsync(p_cnt, 0, NN * sizeof(int), 0);
    k_init_tv<<<gNodeW, T>>>(user, item);
    k_deg<<<gEdge, T>>>(ei);
    k_dinv_partial<<<NBLK, 1024>>>();
    k_scanblocks<<<1, 128>>>();
    k_offsets<<<NBLK, 1024>>>();
    k_fill_sm<<<gDir, T>>>(ei, Sin);

    // ---- 2 layers x 2 routing iterations, 1 fused kernel each ----
    float*  ego  = (float*)p_ego0;
    float*  xn   = (float*)p_ego1;
    float*  tv   = (float*)p_tv0;
    float*  tvn  = (float*)p_tv1;
    float4* ssmA = (float4*)p_ssmA;
    float4* ssmB = (float4*)p_ssmB;

    // layer 0
    k_fused<false, false><<<gNodeW, T>>>(ego, xn, tv, tvn, ssmA, ssmB);
    { float4* t = ssmA; ssmA = ssmB; ssmB = t; }
    k_fused<true,  false><<<gNodeW, T>>>(ego, xn, tv, tvn, ssmA, ssmB);
    { float4* t = ssmA; ssmA = ssmB; ssmB = t; }
    { float* t = ego; ego = xn; xn = t; t = tv; tv = tvn; tvn = t; }
    // layer 1
    k_fused<false, false><<<gNodeW, T>>>(ego, xn, tv, tvn, ssmA, ssmB);
    { float4* t = ssmA; ssmA = ssmB; ssmB = t; }
    k_fused<true,  true ><<<gNodeW, T>>>(ego, xn, tv, tvn, ssmA, ssmB);

    // ---- output: [user_all | item_all | S(4,NE)] ----
    cudaMemcpyAsync(out, p_all, (size_t)NN * D * sizeof(float),
                    cudaMemcpyDeviceToDevice, 0);
    k_transS_out<<<gEdge, T>>>(out + (size_t)NN * D);
}

// round 12
// speedup vs baseline: 1.1314x; 1.1314x over previous
#include <cuda_runtime.h>
#include <math.h>

// Problem constants (fixed by the dataset)
#define NU 60000
#define NI 40000
#define NN 100000     // NU + NI
#define NE 500000
#define D  64
#define NF 4
#define NBLK 98       // ceil(NN/1024) for the scan
#define FULLM 0xFFFFFFFFu

// ---------------- static device scratch ----------------
__device__ float  g_ego0[NN * D];
__device__ float  g_ego1[NN * D];
__device__ float  g_all [NN * D];
__device__ float  g_tv0 [NN * D];    // tv double buffer
__device__ float  g_tv1 [NN * D];
__device__ float4 g_S4  [NE];        // raw S (written only on the final iteration)
__device__ float4 g_SsmA[NE];        // softmax(S) double buffer
__device__ float4 g_SsmB[NE];
__device__ float  g_dinv[NN];
__device__ int    g_deg [NN];
__device__ int    g_rowstart[NN + 1];
__device__ int    g_cnt [NN];
__device__ int    g_blocksum[NBLK];
__device__ float4 g_adj [2 * NE];    // {src, eid, enorm, unused}

// ---------------- setup kernels ----------------

// fused: ego0 = concat(user,item); all = ego0; tv0 = tanh(l2norm_factor(ego0))
// one warp per node
__global__ void k_init_tv(const float* __restrict__ u, const float* __restrict__ it) {
    int gw = (blockIdx.x * blockDim.x + threadIdx.x) >> 5;
    if (gw >= NN) return;
    int lane = threadIdx.x & 31;
    const float* srcp = (gw < NU) ? (u + (size_t)gw * D)
                                  : (it + (size_t)(gw - NU) * D);
    float2 a = reinterpret_cast<const float2*>(srcp)[lane];
    reinterpret_cast<float2*>(g_ego0 + (size_t)gw * D)[lane] = a;
    reinterpret_cast<float2*>(g_all  + (size_t)gw * D)[lane] = a;
    float ss = a.x * a.x + a.y * a.y;
    ss += __shfl_xor_sync(FULLM, ss, 1);
    ss += __shfl_xor_sync(FULLM, ss, 2);
    ss += __shfl_xor_sync(FULLM, ss, 4);
    float rinv = 1.0f / fmaxf(sqrtf(ss), 1e-12f);
    float2 o;
    o.x = tanhf(a.x * rinv);
    o.y = tanhf(a.y * rinv);
    reinterpret_cast<float2*>(g_tv0 + (size_t)gw * D)[lane] = o;
}

__global__ void k_deg(const int* __restrict__ ei) {
    int j = blockIdx.x * blockDim.x + threadIdx.x;
    if (j >= NE) return;
    atomicAdd(&g_deg[ei[j]], 1);
    atomicAdd(&g_deg[ei[NE + j]], 1);
}

// fused: dinv[n] = deg^-0.5 AND per-block partial sums of deg
__global__ void k_dinv_partial() {
    __shared__ int sh[1024];
    int t = threadIdx.x, n = blockIdx.x * 1024 + t;
    int d = (n < NN) ? g_deg[n] : 0;
    if (n < NN) g_dinv[n] = (d > 0) ? (1.0f / sqrtf((float)d)) : 0.0f;
    sh[t] = d;
    __syncthreads();
    for (int o = 512; o > 0; o >>= 1) {
        if (t < o) sh[t] += sh[t + o];
        __syncthreads();
    }
    if (t == 0) g_blocksum[blockIdx.x] = sh[0];
}

// parallel exclusive scan of NBLK block sums (one 128-thread block)
__global__ void k_scanblocks() {
    __shared__ int wsum[4];
    int t = threadIdx.x;                       // 0..127
    int v = (t < NBLK) ? g_blocksum[t] : 0;
    int x = v;
    for (int o = 1; o < 32; o <<= 1) {         // inclusive scan within warp
        int y = __shfl_up_sync(FULLM, x, o);
        if ((t & 31) >= o) x += y;
    }
    if ((t & 31) == 31) wsum[t >> 5] = x;
    __syncthreads();
    if (t == 0) {                              // tiny serial scan of 4 warp sums
        int acc = 0;
        for (int i = 0; i < 4; i++) { int w = wsum[i]; wsum[i] = acc; acc += w; }
    }
    __syncthreads();
    int base = wsum[t >> 5];
    if (t < NBLK) g_blocksum[t] = base + x - v;   // exclusive
    if (t == 0) g_rowstart[NN] = 2 * NE;
}

__global__ void k_offsets() {
    __shared__ int sh[1024];
    int t = threadIdx.x, n = blockIdx.x * 1024 + t;
    int v = (n < NN) ? g_deg[n] : 0;
    sh[t] = v;
    __syncthreads();
    for (int o = 1; o < 1024; o <<= 1) {
        int x = (t >= o) ? sh[t - o] : 0;
        __syncthreads();
        sh[t] += x;
        __syncthreads();
    }
    if (n < NN) g_rowstart[n] = g_blocksum[blockIdx.x] + sh[t] - v;
}

// fill CSR adjacency (both directions); forward thread also computes the
// initial softmax of the input S -> SsmA (fused, saves a separate pass)
__global__ void k_fill_sm(const int* __restrict__ ei, const float* __restrict__ S) {
    int d = blockIdx.x * blockDim.x + threadIdx.x;
    if (d >= 2 * NE) return;
    int j = (d < NE) ? d : d - NE;
    int r = ei[j], c = ei[NE + j];
    int src = (d < NE) ? r : c;
    int dst = (d < NE) ? c : r;
    int pos = g_rowstart[dst] + atomicAdd(&g_cnt[dst], 1);
    g_adj[pos] = make_float4(__int_as_float(src), __int_as_float(j),
                             g_dinv[src] * g_dinv[dst], 0.0f);
    if (d < NE) {
        float4 s = make_float4(S[j], S[NE + j], S[2 * NE + j], S[3 * NE + j]);
        float m  = fmaxf(fmaxf(s.x, s.y), fmaxf(s.z, s.w));
        float e0 = expf(s.x - m), e1 = expf(s.y - m);
        float e2 = expf(s.z - m), e3 = expf(s.w - m);
        float rr = 1.0f / (e0 + e1 + e2 + e3);
        g_SsmA[j] = make_float4(e0 * rr, e1 * rr, e2 * rr, e3 * rr);
    }
}

// broadcast source lane j's per-factor weight vector; return this lane's factor
__device__ __forceinline__ float bcast_w(float4 w4, int j, int kf) {
    float wx = __shfl_sync(FULLM, w4.x, j);
    float wy = __shfl_sync(FULLM, w4.y, j);
    float wz = __shfl_sync(FULLM, w4.z, j);
    float ww = __shfl_sync(FULLM, w4.w, j);
    return (kf == 0) ? wx : (kf == 1) ? wy : (kf == 2) ? wz : ww;
}

// conv over a batch of up to 32 adjacency entries held lane-wise in registers
// (R10 measured sweet spot: unroll x4)
__device__ __forceinline__ void conv_batch(float2& acc, const float* __restrict__ ego,
                                           int src, float4 w4, int n, int lane, int kf) {
    int j = 0;
    for (; j + 4 <= n; j += 4) {
        int s0 = __shfl_sync(FULLM, src, j);
        int s1 = __shfl_sync(FULLM, src, j + 1);
        int s2 = __shfl_sync(FULLM, src, j + 2);
        int s3 = __shfl_sync(FULLM, src, j + 3);
        float2 v0 = *reinterpret_cast<const float2*>(ego + (size_t)s0 * D + lane * 2);
        float2 v1 = *reinterpret_cast<const float2*>(ego + (size_t)s1 * D + lane * 2);
        float2 v2 = *reinterpret_cast<const float2*>(ego + (size_t)s2 * D + lane * 2);
        float2 v3 = *reinterpret_cast<const float2*>(ego + (size_t)s3 * D + lane * 2);
        float w0 = bcast_w(w4, j,     kf);
        float w1 = bcast_w(w4, j + 1, kf);
        float w2 = bcast_w(w4, j + 2, kf);
        float w3 = bcast_w(w4, j + 3, kf);
        acc.x += w0 * v0.x; acc.y += w0 * v0.y;
        acc.x += w1 * v1.x; acc.y += w1 * v1.y;
        acc.x += w2 * v2.x; acc.y += w2 * v2.y;
        acc.x += w3 * v3.x; acc.y += w3 * v3.y;
    }
    for (; j < n; j++) {
        int sj = __shfl_sync(FULLM, src, j);
        float2 v = *reinterpret_cast<const float2*>(ego + (size_t)sj * D + lane * 2);
        float wj = bcast_w(w4, j, kf);
        acc.x += wj * v.x; acc.y += wj * v.y;
    }
}

// score over a batch: returns pp (per-factor dot) for the edge owned by this lane
// (R10 measured sweet spot: unroll x2)
__device__ __forceinline__ float4 score_batch(float2 acc, const float* __restrict__ tv,
                                              int item, int n, int lane) {
    float4 pp = make_float4(0, 0, 0, 0);
    int j = 0;
    for (; j + 2 <= n; j += 2) {
        int i0 = __shfl_sync(FULLM, item, j);
        int i1 = __shfl_sync(FULLM, item, j + 1);
        float2 t0 = *reinterpret_cast<const float2*>(tv + (size_t)i0 * D + lane * 2);
        float2 t1 = *reinterpret_cast<const float2*>(tv + (size_t)i1 * D + lane * 2);
        float pa = acc.x * t0.x + acc.y * t0.y;
        float pb = acc.x * t1.x + acc.y * t1.y;
        pa += __shfl_xor_sync(FULLM, pa, 1);  pb += __shfl_xor_sync(FULLM, pb, 1);
        pa += __shfl_xor_sync(FULLM, pa, 2);  pb += __shfl_xor_sync(FULLM, pb, 2);
        pa += __shfl_xor_sync(FULLM, pa, 4);  pb += __shfl_xor_sync(FULLM, pb, 4);
        float qa0 = __shfl_sync(FULLM, pa, 0),  qa1 = __shfl_sync(FULLM, pa, 8);
        float qa2 = __shfl_sync(FULLM, pa, 16), qa3 = __shfl_sync(FULLM, pa, 24);
        float qb0 = __shfl_sync(FULLM, pb, 0),  qb1 = __shfl_sync(FULLM, pb, 8);
        float qb2 = __shfl_sync(FULLM, pb, 16), qb3 = __shfl_sync(FULLM, pb, 24);
        if (lane == j)     pp = make_float4(qa0, qa1, qa2, qa3);
        if (lane == j + 1) pp = make_float4(qb0, qb1, qb2, qb3);
    }
    for (; j < n; j++) {
        int ij = __shfl_sync(FULLM, item, j);
        float2 t = *reinterpret_cast<const float2*>(tv + (size_t)ij * D + lane * 2);
        float p = acc.x * t.x + acc.y * t.y;
        p += __shfl_xor_sync(FULLM, p, 1);
        p += __shfl_xor_sync(FULLM, p, 2);
        p += __shfl_xor_sync(FULLM, p, 4);
        float q0 = __shfl_sync(FULLM, p, 0),  q1 = __shfl_sync(FULLM, p, 8);
        float q2 = __shfl_sync(FULLM, p, 16), q3 = __shfl_sync(FULLM, p, 24);
        if (lane == j) pp = make_float4(q0, q1, q2, q3);
    }
    return pp;
}

// ---------------- fused conv + score + softmax, one warp per node ----------------
template <bool LASTIT, bool FINAL>
__global__ void __launch_bounds__(256)
k_fused(const float* __restrict__ ego, float* __restrict__ xn,
        const float* __restrict__ tv, float* __restrict__ tv_next,
        const float4* __restrict__ ssm_in, float4* __restrict__ ssm_out) {
    int gw = (blockIdx.x * blockDim.x + threadIdx.x) >> 5;
    if (gw >= NN) return;
    int lane = threadIdx.x & 31;
    int kf = lane >> 3;
    int s = g_rowstart[gw], e = g_rowstart[gw + 1];
    int deg = e - s;

    // ---- phase 1: conv (batch loop + carry registers) ----
    float2 acc = make_float2(0.0f, 0.0f);
    int c_src = 0, c_eid = 0;
    float4 c_sm = make_float4(0, 0, 0, 0);
    for (int b = s; b < e; b += 32) {
        int n = min(32, e - b);
        int src = 0;
        float4 w4 = make_float4(0, 0, 0, 0);
        if (lane < n) {
            float4 a = g_adj[b + lane];                 // coalesced batch load
            src = __float_as_int(a.x);
            float4 sm = ssm_in[__float_as_int(a.y)];    // 32 gathers in flight
            w4 = make_float4(sm.x * a.z, sm.y * a.z, sm.z * a.z, sm.w * a.z);
            c_src = src; c_eid = __float_as_int(a.y); c_sm = sm;   // carry
        }
        conv_batch(acc, ego, src, w4, n, lane, kf);
    }

    reinterpret_cast<float2*>(xn + (size_t)gw * D)[lane] = acc;

    // per-factor inverse norm (every lane ends with its 8-lane group's value)
    float ss = acc.x * acc.x + acc.y * acc.y;
    ss += __shfl_xor_sync(FULLM, ss, 1);
    ss += __shfl_xor_sync(FULLM, ss, 2);
    ss += __shfl_xor_sync(FULLM, ss, 4);
    float rinv = 1.0f / fmaxf(sqrtf(ss), 1e-12f);

    if (LASTIT) {
        float2* ap = reinterpret_cast<float2*>(g_all + (size_t)gw * D) + lane;
        float2 av = *ap;
        av.x += acc.x; av.y += acc.y;
        *ap = av;
        float2 t;
        t.x = tanhf(acc.x * rinv);
        t.y = tanhf(acc.y * rinv);
        reinterpret_cast<float2*>(tv_next + (size_t)gw * D)[lane] = t;
    }

    // ---- phase 2: score (user nodes only) ----
    if (gw >= NU) return;

    float r0 = __shfl_sync(FULLM, rinv, 0);
    float r1 = __shfl_sync(FULLM, rinv, 8);
    float r2 = __shfl_sync(FULLM, rinv, 16);
    float r3 = __shfl_sync(FULLM, rinv, 24);

    if (deg <= 32) {
        // reuse carried registers: c_src (=item), c_eid, c_sm (=raw ssm_in[eid])
        float4 pp = score_batch(acc, tv, c_src, deg, lane);
        if (lane < deg) {
            float4 sv = make_float4(c_sm.x + pp.x * r0, c_sm.y + pp.y * r1,
                                    c_sm.z + pp.z * r2, c_sm.w + pp.w * r3);
            if (FINAL) {
                g_S4[c_eid] = sv;
            } else {
                float m  = fmaxf(fmaxf(sv.x, sv.y), fmaxf(sv.z, sv.w));
                float e0 = expf(sv.x - m), e1 = expf(sv.y - m);
                float e2 = expf(sv.z - m), e3 = expf(sv.w - m);
                float rr = 1.0f / (e0 + e1 + e2 + e3);
                ssm_out[c_eid] = make_float4(e0 * rr, e1 * rr, e2 * rr, e3 * rr);
            }
        }
    } else {
        for (int b = s; b < e; b += 32) {
            int n = min(32, e - b);
            int item = 0, eid = 0;
            float4 svr = make_float4(0, 0, 0, 0);
            if (lane < n) {
                float4 a = g_adj[b + lane];
                item = __float_as_int(a.x);
                eid  = __float_as_int(a.y);
                svr  = ssm_in[eid];
            }
            float4 pp = score_batch(acc, tv, item, n, lane);
            if (lane < n) {
                float4 sv = make_float4(svr.x + pp.x * r0, svr.y + pp.y * r1,
                                        svr.z + pp.z * r2, svr.w + pp.w * r3);
                if (FINAL) {
                    g_S4[eid] = sv;
                } else {
                    float m  = fmaxf(fmaxf(sv.x, sv.y), fmaxf(sv.z, sv.w));
                    float e0 = expf(sv.x - m), e1 = expf(sv.y - m);
                    float e2 = expf(sv.z - m), e3 = expf(sv.w - m);
                    float rr = 1.0f / (e0 + e1 + e2 + e3);
                    ssm_out[eid] = make_float4(e0 * rr, e1 * rr, e2 * rr, e3 * rr);
                }
            }
        }
    }
}

// output S transpose [NE,4] -> [4,NE]
__global__ void k_transS_out(float* __restrict__ outS) {
    int j = blockIdx.x * blockDim.x + threadIdx.x;
    if (j >= NE) return;
    float4 s = g_S4[j];
    outS[j]          = s.x;
    outS[NE + j]     = s.y;
    outS[2 * NE + j] = s.z;
    outS[3 * NE + j] = s.w;
}

// ---------------- host orchestration ----------------

extern "C" void kernel_launch(void* const* d_in, const int* in_sizes, int n_in,
                              void* d_out, int out_size) {
    const float* user = (const float*)d_in[0];
    const float* item = (const float*)d_in[1];
    const float* Sin  = (const float*)d_in[2];
    const int*   ei   = (const int*)d_in[3];
    float* out = (float*)d_out;

    void *p_deg, *p_cnt, *p_ego0, *p_ego1, *p_all, *p_tv0, *p_tv1, *p_ssmA, *p_ssmB;
    cudaGetSymbolAddress(&p_deg,  g_deg);
    cudaGetSymbolAddress(&p_cnt,  g_cnt);
    cudaGetSymbolAddress(&p_ego0, g_ego0);
    cudaGetSymbolAddress(&p_ego1, g_ego1);
    cudaGetSymbolAddress(&p_all,  g_all);
    cudaGetSymbolAddress(&p_tv0,  g_tv0);
    cudaGetSymbolAddress(&p_tv1,  g_tv1);
    cudaGetSymbolAddress(&p_ssmA, g_SsmA);
    cudaGetSymbolAddress(&p_ssmB, g_SsmB);

    const int T = 256;
    const int gEdge  = (NE + T - 1) / T;
    const int gDir   = (2 * NE + T - 1) / T;
    const int gNodeW = (NN * 32 + T - 1) / T;

    // ---- setup (6 kernels + 2 memsets) ----
    cudaMemsetAsync(p_deg, 0, NN * sizeof(int), 0);
    cudaMemsetAsync(p_cnt, 0, NN * sizeof(int), 0);
    k_init_tv<<<gNodeW, T>>>(user, item);
    k_deg<<<gEdge, T>>>(ei);
    k_dinv_partial<<<NBLK, 1024>>>();
    k_scanblocks<<<1, 128>>>();
    k_offsets<<<NBLK, 1024>>>();
    k_fill_sm<<<gDir, T>>>(ei, Sin);

    // ---- 2 layers x 2 routing iterations, 1 fused kernel each ----
    float*  ego  = (float*)p_ego0;
    float*  xn   = (float*)p_ego1;
    float*  tv   = (float*)p_tv0;
    float*  tvn  = (float*)p_tv1;
    float4* ssmA = (float4*)p_ssmA;
    float4* ssmB = (float4*)p_ssmB;

    // layer 0
    k_fused<false, false><<<gNodeW, T>>>(ego, xn, tv, tvn, ssmA, ssmB);
    { float4* t = ssmA; ssmA = ssmB; ssmB = t; }
    k_fused<true,  false><<<gNodeW, T>>>(ego, xn, tv, tvn, ssmA, ssmB);
    { float4* t = ssmA; ssmA = ssmB; ssmB = t; }
    { float* t = ego; ego = xn; xn = t; t = tv; tv = tvn; tvn = t; }
    // layer 1
    k_fused<false, false><<<gNodeW, T>>>(ego, xn, tv, tvn, ssmA, ssmB);
    { float4* t = ssmA; ssmA = ssmB; ssmB = t; }
    k_fused<true,  true ><<<gNodeW, T>>>(ego, xn, tv, tvn, ssmA, ssmB);

    // ---- output: [user_all | item_all | S(4,NE)] ----
    cudaMemcpyAsync(out, p_all, (size_t)NN * D * sizeof(float),
                    cudaMemcpyDeviceToDevice, 0);
    k_transS_out<<<gEdge, T>>>(out + (size_t)NN * D);
}